// round 3
// baseline (speedup 1.0000x reference)
#include <cuda_runtime.h>
#include <cstddef>

// GRU (B rows, T=1024, D=6, H=48) + fused FC.
// Block = 96 threads (3 warps), R=4 batch rows.
// Warp w owns outputs i = w*16 + (lane%16); k-half s = lane/16.
// k-split reduction via __shfl_xor(16) (intra-warp) -> ONE barrier per step.
// W_hh half-rows + full W_ih rows in registers; h pingpong in shared.

#define T_SEQ 1024
#define D_IN  6
#define HDIM  48
#define KH    24
#define R     4
#define NTHR  96

__device__ __forceinline__ float2 ffma2(float2 a, float2 b, float2 c) {
    union U { float2 f; unsigned long long u; };
    U ua, ub, uc, ud;
    ua.f = a; ub.f = b; uc.f = c;
    asm("fma.rn.f32x2 %0, %1, %2, %3;" : "=l"(ud.u) : "l"(ua.u), "l"(ub.u), "l"(uc.u));
    return ud.f;
}

__device__ __forceinline__ float fast_sigmoid(float x) {
    float e = __expf(-x);
    return __fdividef(1.0f, 1.0f + e);
}
__device__ __forceinline__ float fast_tanh(float x) {
    float a = fabsf(x);
    float e = __expf(2.0f * a);
    float r = 1.0f - __fdividef(2.0f, e + 1.0f);
    return copysignf(r, x);
}

__global__ void __launch_bounds__(NTHR, 4)
gru_fused_kernel(const float* __restrict__ x,
                 const float* __restrict__ W_ih,   // [144, 6]
                 const float* __restrict__ W_hh,   // [144, 48]
                 const float* __restrict__ b_ih,   // [144]
                 const float* __restrict__ b_hh,   // [144]
                 const float* __restrict__ fc_w,   // [6, 48]
                 const float* __restrict__ fc_b,   // [6]
                 float* __restrict__ y,            // [B, T, 6]
                 int B)
{
    __shared__ __align__(16) float h_s[2][R][HDIM];
    __shared__ __align__(16) float x_s[2][R][8];

    const int tid  = threadIdx.x;
    const int w    = tid >> 5;
    const int lane = tid & 31;
    const int s    = lane >> 4;          // k-half
    const int io   = lane & 15;
    const int i    = w * 16 + io;        // owned output index 0..47
    const int b0   = blockIdx.x * R;

    // ---- recurrent weights: W_hh[g*48+i][s*24 .. s*24+23] -> 12 f32x2 / gate ----
    float2 whr[12], whz[12], whn[12];
    {
        const float4* pr = reinterpret_cast<const float4*>(W_hh + ((size_t)(0 * HDIM + i) * HDIM + s * KH));
        const float4* pz = reinterpret_cast<const float4*>(W_hh + ((size_t)(1 * HDIM + i) * HDIM + s * KH));
        const float4* pn = reinterpret_cast<const float4*>(W_hh + ((size_t)(2 * HDIM + i) * HDIM + s * KH));
        #pragma unroll
        for (int q = 0; q < 6; q++) {
            float4 v;
            v = pr[q]; whr[2*q] = make_float2(v.x, v.y); whr[2*q+1] = make_float2(v.z, v.w);
            v = pz[q]; whz[2*q] = make_float2(v.x, v.y); whz[2*q+1] = make_float2(v.z, v.w);
            v = pn[q]; whn[2*q] = make_float2(v.x, v.y); whn[2*q+1] = make_float2(v.z, v.w);
        }
    }
    // ---- input weights, full D (both halves redundant) ----
    float2 wir[3], wiz[3], win[3];
    {
        const float2* pr = reinterpret_cast<const float2*>(W_ih + (size_t)(0 * HDIM + i) * D_IN);
        const float2* pz = reinterpret_cast<const float2*>(W_ih + (size_t)(1 * HDIM + i) * D_IN);
        const float2* pn = reinterpret_cast<const float2*>(W_ih + (size_t)(2 * HDIM + i) * D_IN);
        #pragma unroll
        for (int j = 0; j < 3; j++) { wir[j] = pr[j]; wiz[j] = pz[j]; win[j] = pn[j]; }
    }
    const float brr = b_ih[i]            + b_hh[i];
    const float bzz = b_ih[HDIM + i]     + b_hh[HDIM + i];
    const float bin = b_ih[2 * HDIM + i];
    const float bhn = b_hh[2 * HDIM + i];

    // ---- fc role: thread handles rows rcA and rcA+2, output d_fc, k-chunk c_fc ----
    const int i2   = tid % HDIM;
    const int rcA  = tid / HDIM;         // 0 or 1
    const int d_fc = i2 >> 3;
    const int c_fc = i2 & 7;
    float2 fw[3];
    {
        const float2* p = reinterpret_cast<const float2*>(fc_w + (size_t)d_fc * HDIM + c_fc * 6);
        fw[0] = p[0]; fw[1] = p[1]; fw[2] = p[2];
    }
    const float fb = fc_b[d_fc];
    float* yA = y + (size_t)(b0 + rcA)     * T_SEQ * D_IN;
    float* yB = y + (size_t)(b0 + rcA + 2) * T_SEQ * D_IN;
    const bool vA = (b0 + rcA)     < B;
    const bool vB = (b0 + rcA + 2) < B;

    // ---- init ----
    float hc[R];
    #pragma unroll
    for (int r = 0; r < R; r++) hc[r] = 0.0f;
    if (s == 0) {
        #pragma unroll
        for (int r = 0; r < R; r++) h_s[0][r][i] = 0.0f;
    }
    if (tid < R * D_IN) {
        int rr = tid / D_IN, dd = tid - rr * D_IN;
        x_s[0][rr][dd] = ((b0 + rr) < B) ? x[((size_t)(b0 + rr) * T_SEQ) * D_IN + dd] : 0.0f;
    }
    __syncthreads();

    const float2 z2 = make_float2(0.0f, 0.0f);
    int p = 0;

    for (int t = 0; t < T_SEQ; t++) {
        // ---- prefetch x[t+1] ----
        float xn = 0.0f;
        if (tid < R * D_IN && (t + 1) < T_SEQ) {
            int rr = tid / D_IN, dd = tid - rr * D_IN;
            if ((b0 + rr) < B) xn = x[((size_t)(b0 + rr) * T_SEQ + (t + 1)) * D_IN + dd];
        }

        // ---- P1: gh half-dots + full gi, all R rows (pure FMA, high ILP) ----
        float ghr[R], ghz[R], ghn[R], gr_[R], gz_[R], gn_[R];
        #pragma unroll
        for (int r = 0; r < R; r++) {
            float2 a_r = z2, a_z = z2, a_n = z2;
            const float4* h4 = reinterpret_cast<const float4*>(&h_s[p][r][s * KH]);
            #pragma unroll
            for (int q = 0; q < 6; q++) {
                float4 hv = h4[q];
                float2 h01 = make_float2(hv.x, hv.y);
                float2 h23 = make_float2(hv.z, hv.w);
                a_r = ffma2(whr[2*q], h01, a_r); a_r = ffma2(whr[2*q+1], h23, a_r);
                a_z = ffma2(whz[2*q], h01, a_z); a_z = ffma2(whz[2*q+1], h23, a_z);
                a_n = ffma2(whn[2*q], h01, a_n); a_n = ffma2(whn[2*q+1], h23, a_n);
            }
            float2 g_r = z2, g_z = z2, g_n = z2;
            const float2* xp = reinterpret_cast<const float2*>(x_s[p][r]);
            #pragma unroll
            for (int j = 0; j < 3; j++) {
                float2 xv = xp[j];
                g_r = ffma2(wir[j], xv, g_r);
                g_z = ffma2(wiz[j], xv, g_z);
                g_n = ffma2(win[j], xv, g_n);
            }
            ghr[r] = a_r.x + a_r.y;  ghz[r] = a_z.x + a_z.y;  ghn[r] = a_n.x + a_n.y;
            gr_[r] = g_r.x + g_r.y;  gz_[r] = g_z.x + g_z.y;  gn_[r] = g_n.x + g_n.y;
        }

        // ---- fused fc on h_{t-1} (reads h_s[p], still valid) ----
        if (t > 0) {
            const float2* hcA = reinterpret_cast<const float2*>(&h_s[p][rcA][c_fc * 6]);
            const float2* hcB = reinterpret_cast<const float2*>(&h_s[p][rcA + 2][c_fc * 6]);
            float2 aA = ffma2(fw[0], hcA[0], z2);
            aA = ffma2(fw[1], hcA[1], aA);
            aA = ffma2(fw[2], hcA[2], aA);
            float2 aB = ffma2(fw[0], hcB[0], z2);
            aB = ffma2(fw[1], hcB[1], aB);
            aB = ffma2(fw[2], hcB[2], aB);
            float pA = aA.x + aA.y;
            float pB = aB.x + aB.y;
            pA += __shfl_down_sync(0xffffffffu, pA, 4, 8);
            pB += __shfl_down_sync(0xffffffffu, pB, 4, 8);
            pA += __shfl_down_sync(0xffffffffu, pA, 2, 8);
            pB += __shfl_down_sync(0xffffffffu, pB, 2, 8);
            pA += __shfl_down_sync(0xffffffffu, pA, 1, 8);
            pB += __shfl_down_sync(0xffffffffu, pB, 1, 8);
            if (c_fc == 0) {
                if (vA) yA[(size_t)(t - 1) * D_IN + d_fc] = pA + fb;
                if (vB) yB[(size_t)(t - 1) * D_IN + d_fc] = pB + fb;
            }
        }

        // ---- k-half exchange (intra-warp) ----
        #pragma unroll
        for (int r = 0; r < R; r++) {
            ghr[r] += __shfl_xor_sync(0xffffffffu, ghr[r], 16);
            ghz[r] += __shfl_xor_sync(0xffffffffu, ghz[r], 16);
            ghn[r] += __shfl_xor_sync(0xffffffffu, ghn[r], 16);
        }

        // ---- gates + state update (redundant in both halves) ----
        #pragma unroll
        for (int r = 0; r < R; r++) {
            float rg = fast_sigmoid(ghr[r] + gr_[r] + brr);
            float zg = fast_sigmoid(ghz[r] + gz_[r] + bzz);
            float ng = fast_tanh((gn_[r] + bin) + rg * (ghn[r] + bhn));
            hc[r] = ng + zg * (hc[r] - ng);
            if (s == 0) h_s[p ^ 1][r][i] = hc[r];
        }
        if (tid < R * D_IN) {
            int rr = tid / D_IN, dd = tid - rr * D_IN;
            x_s[p ^ 1][rr][dd] = xn;
        }
        __syncthreads();
        p ^= 1;
    }

    // ---- fc for final h_{T-1} ----
    {
        const float2* hcA = reinterpret_cast<const float2*>(&h_s[p][rcA][c_fc * 6]);
        const float2* hcB = reinterpret_cast<const float2*>(&h_s[p][rcA + 2][c_fc * 6]);
        float2 aA = ffma2(fw[0], hcA[0], z2);
        aA = ffma2(fw[1], hcA[1], aA);
        aA = ffma2(fw[2], hcA[2], aA);
        float2 aB = ffma2(fw[0], hcB[0], z2);
        aB = ffma2(fw[1], hcB[1], aB);
        aB = ffma2(fw[2], hcB[2], aB);
        float pA = aA.x + aA.y;
        float pB = aB.x + aB.y;
        pA += __shfl_down_sync(0xffffffffu, pA, 4, 8);
        pB += __shfl_down_sync(0xffffffffu, pB, 4, 8);
        pA += __shfl_down_sync(0xffffffffu, pA, 2, 8);
        pB += __shfl_down_sync(0xffffffffu, pB, 2, 8);
        pA += __shfl_down_sync(0xffffffffu, pA, 1, 8);
        pB += __shfl_down_sync(0xffffffffu, pB, 1, 8);
        if (c_fc == 0) {
            if (vA) yA[(size_t)(T_SEQ - 1) * D_IN + d_fc] = pA + fb;
            if (vB) yB[(size_t)(T_SEQ - 1) * D_IN + d_fc] = pB + fb;
        }
    }
}

extern "C" void kernel_launch(void* const* d_in, const int* in_sizes, int n_in,
                              void* d_out, int out_size)
{
    const float* x    = (const float*)d_in[0];
    const float* W_ih = (const float*)d_in[1];
    const float* W_hh = (const float*)d_in[2];
    const float* b_ih = (const float*)d_in[3];
    const float* b_hh = (const float*)d_in[4];
    const float* fc_w = (const float*)d_in[5];
    const float* fc_b = (const float*)d_in[6];
    float* y = (float*)d_out;

    int B = in_sizes[0] / (T_SEQ * D_IN);
    int blocks = (B + R - 1) / R;
    gru_fused_kernel<<<blocks, NTHR>>>(x, W_ih, W_hh, b_ih, b_hh, fc_w, fc_b, y, B);
}

// round 4
// speedup vs baseline: 1.0985x; 1.0985x over previous
#include <cuda_runtime.h>
#include <cstddef>

// GRU (B rows, T=1024, D=6, H=48) + fused FC.
// Block = 96 threads, R=3 batch rows -> grid 683 = single wave at 5 blk/SM.
// Computer role: thread (s=tid/48, i=tid%48) computes k-half s of all 3 gate
// dots for output i, all 3 rows (weight-register reuse). Partials exchanged as
// ONE float4 per (s,row,i) in smem. Combine role: rows 0/1 one per thread,
// row 2 on threads 0-47. Two barriers/step; single-buffered h_s and x_s.

#define T_SEQ 1024
#define D_IN  6
#define HDIM  48
#define KH    24
#define R     3
#define NTHR  96

__device__ __forceinline__ float2 ffma2(float2 a, float2 b, float2 c) {
    union U { float2 f; unsigned long long u; };
    U ua, ub, uc, ud;
    ua.f = a; ub.f = b; uc.f = c;
    asm("fma.rn.f32x2 %0, %1, %2, %3;" : "=l"(ud.u) : "l"(ua.u), "l"(ub.u), "l"(uc.u));
    return ud.f;
}

__device__ __forceinline__ float fast_sigmoid(float x) {
    float e = __expf(-x);
    return __fdividef(1.0f, 1.0f + e);
}
__device__ __forceinline__ float fast_tanh(float x) {
    float a = fabsf(x);
    float e = __expf(2.0f * a);
    float r = 1.0f - __fdividef(2.0f, e + 1.0f);
    return copysignf(r, x);
}

__global__ void __launch_bounds__(NTHR, 5)
gru_fused_kernel(const float* __restrict__ x,
                 const float* __restrict__ W_ih,   // [144, 6]
                 const float* __restrict__ W_hh,   // [144, 48]
                 const float* __restrict__ b_ih,   // [144]
                 const float* __restrict__ b_hh,   // [144]
                 const float* __restrict__ fc_w,   // [6, 48]
                 const float* __restrict__ fc_b,   // [6]
                 float* __restrict__ y,            // [B, T, 6]
                 int B)
{
    __shared__ __align__(16) float  h_s[R][HDIM];
    __shared__ __align__(16) float4 p_s[2][R][HDIM];   // packed {r, z, ghn, gin}
    __shared__ __align__(16) float  x_s[R][8];

    const int tid = threadIdx.x;
    const int s   = tid / HDIM;          // k-half (computer role)
    const int i   = tid - s * HDIM;      // output index 0..47
    const int b0  = blockIdx.x * R;

    const bool v0 = (b0 + 0) < B;
    const bool v1 = (b0 + 1) < B;
    const bool v2 = (b0 + 2) < B;

    // ---- computer weights: W_hh[g*48+i][s*24..s*24+23] -> 12 f32x2 per gate ----
    float2 whr[12], whz[12], whn[12];
    {
        const float4* pr = reinterpret_cast<const float4*>(W_hh + ((size_t)(0 * HDIM + i) * HDIM + s * KH));
        const float4* pz = reinterpret_cast<const float4*>(W_hh + ((size_t)(1 * HDIM + i) * HDIM + s * KH));
        const float4* pn = reinterpret_cast<const float4*>(W_hh + ((size_t)(2 * HDIM + i) * HDIM + s * KH));
        #pragma unroll
        for (int q = 0; q < 6; q++) {
            float4 v;
            v = pr[q]; whr[2*q] = make_float2(v.x, v.y); whr[2*q+1] = make_float2(v.z, v.w);
            v = pz[q]; whz[2*q] = make_float2(v.x, v.y); whz[2*q+1] = make_float2(v.z, v.w);
            v = pn[q]; whn[2*q] = make_float2(v.x, v.y); whn[2*q+1] = make_float2(v.z, v.w);
        }
    }
    // gi weights: W_ih[g*48+i][s*3 .. s*3+2]
    float wir[3], wiz[3], win[3];
    #pragma unroll
    for (int j = 0; j < 3; j++) {
        wir[j] = W_ih[(size_t)(0 * HDIM + i) * D_IN + s * 3 + j];
        wiz[j] = W_ih[(size_t)(1 * HDIM + i) * D_IN + s * 3 + j];
        win[j] = W_ih[(size_t)(2 * HDIM + i) * D_IN + s * 3 + j];
    }

    // ---- combiner biases (output index i; both of a thread's combines share i) ----
    const float brr = b_ih[i]            + b_hh[i];
    const float bzz = b_ih[HDIM + i]     + b_hh[HDIM + i];
    const float bin = b_ih[2 * HDIM + i];
    const float bhn = b_hh[2 * HDIM + i];

    // ---- fc role: slot = (row rcA = tid/48, d = i>>3, c = i&7); tid<48 also row 2 ----
    const int d_fc = i >> 3;
    const int c_fc = i & 7;
    float2 fw[3];
    {
        const float2* p = reinterpret_cast<const float2*>(fc_w + (size_t)d_fc * HDIM + c_fc * 6);
        fw[0] = p[0]; fw[1] = p[1]; fw[2] = p[2];
    }
    const float fb = fc_b[d_fc];
    const int  rcA = s;                               // 0 or 1
    float* yA = y + (size_t)(b0 + rcA) * T_SEQ * D_IN;
    float* yC = y + (size_t)(b0 + 2)   * T_SEQ * D_IN;
    const bool vA = (b0 + rcA) < B;
    const unsigned mask2 = (tid < 32) ? 0xFFFFFFFFu : 0x0000FFFFu;  // for row-2 half-warp shfl

    // ---- init ----
    float hc1 = 0.0f, hc2 = 0.0f;        // combiner-owned states
    if (tid < HDIM) { h_s[0][i] = 0.0f; h_s[2][i] = 0.0f; }
    else            { h_s[1][i] = 0.0f; }
    if (tid < R * D_IN) {
        int rr = tid / D_IN, dd = tid - rr * D_IN;
        x_s[rr][dd] = ((b0 + rr) < B) ? x[((size_t)(b0 + rr) * T_SEQ) * D_IN + dd] : 0.0f;
    }
    __syncthreads();

    const float2 z2 = make_float2(0.0f, 0.0f);

    for (int t = 0; t < T_SEQ; t++) {
        // ---- prefetch x[t+1] ----
        float xn = 0.0f;
        if (tid < R * D_IN && (t + 1) < T_SEQ) {
            int rr = tid / D_IN, dd = tid - rr * D_IN;
            if ((b0 + rr) < B) xn = x[((size_t)(b0 + rr) * T_SEQ + (t + 1)) * D_IN + dd];
        }

        // ================= P1: half-dots for all R rows (pure FMA, high ILP) ====
        #pragma unroll
        for (int r = 0; r < R; r++) {
            float2 a_r = z2, a_z = z2, a_n = z2;
            const float4* h4 = reinterpret_cast<const float4*>(&h_s[r][s * KH]);
            #pragma unroll
            for (int q = 0; q < 6; q++) {
                float4 hv = h4[q];
                float2 h01 = make_float2(hv.x, hv.y);
                float2 h23 = make_float2(hv.z, hv.w);
                a_r = ffma2(whr[2*q], h01, a_r); a_r = ffma2(whr[2*q+1], h23, a_r);
                a_z = ffma2(whz[2*q], h01, a_z); a_z = ffma2(whz[2*q+1], h23, a_z);
                a_n = ffma2(whn[2*q], h01, a_n); a_n = ffma2(whn[2*q+1], h23, a_n);
            }
            float g_r = 0.f, g_z = 0.f, g_n = 0.f;
            #pragma unroll
            for (int j = 0; j < 3; j++) {
                float xv = x_s[r][s * 3 + j];
                g_r = fmaf(wir[j], xv, g_r);
                g_z = fmaf(wiz[j], xv, g_z);
                g_n = fmaf(win[j], xv, g_n);
            }
            float4 pk;
            pk.x = a_r.x + a_r.y + g_r;
            pk.y = a_z.x + a_z.y + g_z;
            pk.z = a_n.x + a_n.y;        // gh_n half (kept separate from gi_n)
            pk.w = g_n;                   // gi_n half
            p_s[s][r][i] = pk;            // one STS.128
        }

        // ---- fused fc on h_{t-1} (reads h_s before BAR1) ----
        if (t > 0) {
            const float2* hcA = reinterpret_cast<const float2*>(&h_s[rcA][c_fc * 6]);
            float2 aA = ffma2(fw[0], hcA[0], z2);
            aA = ffma2(fw[1], hcA[1], aA);
            aA = ffma2(fw[2], hcA[2], aA);
            float pA = aA.x + aA.y;
            pA += __shfl_down_sync(0xffffffffu, pA, 4, 8);
            pA += __shfl_down_sync(0xffffffffu, pA, 2, 8);
            pA += __shfl_down_sync(0xffffffffu, pA, 1, 8);
            if (c_fc == 0 && vA) yA[(size_t)(t - 1) * D_IN + d_fc] = pA + fb;
            if (tid < HDIM) {
                const float2* hcC = reinterpret_cast<const float2*>(&h_s[2][c_fc * 6]);
                float2 aC = ffma2(fw[0], hcC[0], z2);
                aC = ffma2(fw[1], hcC[1], aC);
                aC = ffma2(fw[2], hcC[2], aC);
                float pC = aC.x + aC.y;
                pC += __shfl_down_sync(mask2, pC, 4, 8);
                pC += __shfl_down_sync(mask2, pC, 2, 8);
                pC += __shfl_down_sync(mask2, pC, 1, 8);
                if (c_fc == 0 && v2) yC[(size_t)(t - 1) * D_IN + d_fc] = pC + fb;
            }
        }
        __syncthreads();   // BAR1: partials in p_s; h_s free to overwrite

        // ================= P2: combine + gates =================
        {
            const int rc1 = s;                         // row 0 (tid<48) or row 1
            float4 a = p_s[0][rc1][i];
            float4 b = p_s[1][rc1][i];
            float rg = fast_sigmoid(a.x + b.x + brr);
            float zg = fast_sigmoid(a.y + b.y + bzz);
            float ng = fast_tanh((a.w + b.w + bin) + rg * (a.z + b.z + bhn));
            hc1 = ng + zg * (hc1 - ng);
            h_s[rc1][i] = hc1;
        }
        if (tid < HDIM) {                              // row 2
            float4 a = p_s[0][2][i];
            float4 b = p_s[1][2][i];
            float rg = fast_sigmoid(a.x + b.x + brr);
            float zg = fast_sigmoid(a.y + b.y + bzz);
            float ng = fast_tanh((a.w + b.w + bin) + rg * (a.z + b.z + bhn));
            hc2 = ng + zg * (hc2 - ng);
            h_s[2][i] = hc2;
        }
        if (tid < R * D_IN) {
            int rr = tid / D_IN, dd = tid - rr * D_IN;
            x_s[rr][dd] = xn;
        }
        __syncthreads();   // BAR2: h_t + x_{t+1} visible
    }

    // ---- fc for final h_{T-1} ----
    {
        const float2* hcA = reinterpret_cast<const float2*>(&h_s[rcA][c_fc * 6]);
        float2 aA = ffma2(fw[0], hcA[0], z2);
        aA = ffma2(fw[1], hcA[1], aA);
        aA = ffma2(fw[2], hcA[2], aA);
        float pA = aA.x + aA.y;
        pA += __shfl_down_sync(0xffffffffu, pA, 4, 8);
        pA += __shfl_down_sync(0xffffffffu, pA, 2, 8);
        pA += __shfl_down_sync(0xffffffffu, pA, 1, 8);
        if (c_fc == 0 && vA) yA[(size_t)(T_SEQ - 1) * D_IN + d_fc] = pA + fb;
        if (tid < HDIM) {
            const float2* hcC = reinterpret_cast<const float2*>(&h_s[2][c_fc * 6]);
            float2 aC = ffma2(fw[0], hcC[0], z2);
            aC = ffma2(fw[1], hcC[1], aC);
            aC = ffma2(fw[2], hcC[2], aC);
            float pC = aC.x + aC.y;
            pC += __shfl_down_sync(mask2, pC, 4, 8);
            pC += __shfl_down_sync(mask2, pC, 2, 8);
            pC += __shfl_down_sync(mask2, pC, 1, 8);
            if (c_fc == 0 && v2) yC[(size_t)(T_SEQ - 1) * D_IN + d_fc] = pC + fb;
        }
    }
    (void)v0; (void)v1;
}

extern "C" void kernel_launch(void* const* d_in, const int* in_sizes, int n_in,
                              void* d_out, int out_size)
{
    const float* x    = (const float*)d_in[0];
    const float* W_ih = (const float*)d_in[1];
    const float* W_hh = (const float*)d_in[2];
    const float* b_ih = (const float*)d_in[3];
    const float* b_hh = (const float*)d_in[4];
    const float* fc_w = (const float*)d_in[5];
    const float* fc_b = (const float*)d_in[6];
    float* y = (float*)d_out;

    int B = in_sizes[0] / (T_SEQ * D_IN);
    int blocks = (B + R - 1) / R;
    gru_fused_kernel<<<blocks, NTHR>>>(x, W_ih, W_hh, b_ih, b_hh, fc_w, fc_b, y, B);
}